// round 1
// baseline (speedup 1.0000x reference)
#include <cuda_runtime.h>

#define NN   100000
#define NE   1600000
#define HID  64
#define TXT  384
#define NBATCH 1024
#define NB_SCAN 98            // ceil(NN/1024)

// ---------------- scratch (device globals; no allocation allowed) ----------
__device__ int   d_row_f[NN + 1];
__device__ int   d_row_r[NN + 1];
__device__ int   d_cur_f[NN];
__device__ int   d_cur_r[NN];
__device__ int   d_enb_f[NE];
__device__ float d_ew_f[NE];
__device__ int   d_enb_r[NE];
__device__ float d_ew_r[NE];
__device__ float d_x [NN * HID];
__device__ float d_nf[NN * HID];
__device__ float d_nr[NN * HID];
__device__ int   d_bsum[256];

// ---------------- CSR construction -----------------------------------------
__global__ void k_zero() {
    int i = blockIdx.x * blockDim.x + threadIdx.x;
    if (i < NN) { d_cur_f[i] = 0; d_cur_r[i] = 0; }
}

__global__ void k_hist(const int* __restrict__ src, const int* __restrict__ dst) {
    for (int e = blockIdx.x * blockDim.x + threadIdx.x; e < NE;
         e += gridDim.x * blockDim.x) {
        atomicAdd(&d_cur_f[dst[e]], 1);   // forward: in-degree at dst
        atomicAdd(&d_cur_r[src[e]], 1);   // reverse: degree at src
    }
}

__global__ void k_scan1(int which) {
    const int* cnt = which ? d_cur_r : d_cur_f;
    int*       row = which ? d_row_r : d_row_f;
    __shared__ int s[1024];
    int t = threadIdx.x;
    int i = blockIdx.x * 1024 + t;
    int v = (i < NN) ? cnt[i] : 0;
    s[t] = v; __syncthreads();
    for (int off = 1; off < 1024; off <<= 1) {
        int add = (t >= off) ? s[t - off] : 0;
        __syncthreads();
        s[t] += add;
        __syncthreads();
    }
    if (i < NN) row[i] = s[t] - v;                 // exclusive within block
    if (t == 1023) d_bsum[which * 128 + blockIdx.x] = s[1023];
}

__global__ void k_scan2(int which) {
    __shared__ int s[128];
    int t = threadIdx.x;
    int v = (t < NB_SCAN) ? d_bsum[which * 128 + t] : 0;
    s[t] = v; __syncthreads();
    for (int off = 1; off < 128; off <<= 1) {
        int add = (t >= off) ? s[t - off] : 0;
        __syncthreads();
        s[t] += add;
        __syncthreads();
    }
    d_bsum[which * 128 + t] = s[t] - v;            // exclusive block offsets
}

__global__ void k_scan3(int which) {
    int* row = which ? d_row_r : d_row_f;
    int* cur = which ? d_cur_r : d_cur_f;
    int i = blockIdx.x * blockDim.x + threadIdx.x;
    if (i < NN) {
        int r = row[i] + d_bsum[which * 128 + (i >> 10)];
        row[i] = r;
        cur[i] = r;
    }
    if (i == 0) row[NN] = NE;
}

__global__ void k_fill(const int* __restrict__ src, const int* __restrict__ dst,
                       const float* __restrict__ w) {
    for (int e = blockIdx.x * blockDim.x + threadIdx.x; e < NE;
         e += gridDim.x * blockDim.x) {
        int s = src[e], d = dst[e]; float ww = w[e];
        int p = atomicAdd(&d_cur_f[d], 1);
        d_enb_f[p] = s; d_ew_f[p] = ww;
        int q = atomicAdd(&d_cur_r[s], 1);
        d_enb_r[q] = d; d_ew_r[q] = ww;
    }
}

// ---------------- encoder: x = text @ W_enc + b_enc ------------------------
// warp per row; W_enc staged in smem; lane owns output cols (2L, 2L+1).
__global__ void k_encoder(const float* __restrict__ text,
                          const float* __restrict__ Wenc,
                          const float* __restrict__ benc) {
    extern __shared__ float sm[];      // [TXT*HID] weights, then [HID] bias
    float* sW = sm;
    float* sb = sm + TXT * HID;
    for (int i = threadIdx.x; i < TXT * HID; i += blockDim.x) sW[i] = Wenc[i];
    if (threadIdx.x < HID) sb[threadIdx.x] = benc[threadIdx.x];
    __syncthreads();

    int lane = threadIdx.x & 31;
    int row  = blockIdx.x * 32 + (threadIdx.x >> 5);
    if (row >= NN) return;

    const float* tr = text + (long long)row * TXT;
    float a0 = sb[2 * lane], a1 = sb[2 * lane + 1];
    for (int k0 = 0; k0 < TXT; k0 += 32) {
        float t = tr[k0 + lane];
#pragma unroll
        for (int j = 0; j < 32; ++j) {
            float xk = __shfl_sync(0xFFFFFFFFu, t, j);
            float2 w = *(const float2*)(sW + (k0 + j) * HID + 2 * lane);
            a0 = fmaf(xk, w.x, a0);
            a1 = fmaf(xk, w.y, a1);
        }
    }
    ((float2*)(d_x + (long long)row * HID))[lane] = make_float2(a0, a1);
}

// ---------------- gather-based mean aggregation ----------------------------
// warp per node; lane owns cols (2L, 2L+1); gathers are 256B coalesced.
__global__ void k_agg(int which) {
    int lane = threadIdx.x & 31;
    int v = blockIdx.x * (blockDim.x >> 5) + (threadIdx.x >> 5);
    if (v >= NN) return;
    const int*   row = which ? d_row_r : d_row_f;
    const int*   enb = which ? d_enb_r : d_enb_f;
    const float* ew  = which ? d_ew_r  : d_ew_f;
    float*       out = which ? d_nr    : d_nf;

    int beg = row[v], end = row[v + 1];
    float a0 = 0.f, a1 = 0.f;
    for (int e = beg; e < end; ++e) {
        int u = enb[e]; float wv = ew[e];
        float2 xv = *(const float2*)(d_x + (long long)u * HID + 2 * lane);
        a0 = fmaf(wv, xv.x, a0);
        a1 = fmaf(wv, xv.y, a1);
    }
    float inv = (end > beg) ? 1.0f / (float)(end - beg) : 0.f;
    ((float2*)(out + (long long)v * HID))[lane] = make_float2(a0 * inv, a1 * inv);
}

// ---------------- dense layer update (layer 0, all nodes, in-place) --------
// x <- x + relu(x@Wsf + nf@Wnf + bf) + relu(x@Wsr + nr@Wnr + br)
__global__ void k_update(const float* __restrict__ Wsf, const float* __restrict__ Wnf,
                         const float* __restrict__ bf,
                         const float* __restrict__ Wsr, const float* __restrict__ Wnr,
                         const float* __restrict__ br) {
    extern __shared__ float sm[];
    float *sWsf = sm, *sWnf = sm + 4096, *sWsr = sm + 8192, *sWnr = sm + 12288;
    float *sbf  = sm + 16384, *sbr = sm + 16448;
    for (int i = threadIdx.x; i < 4096; i += blockDim.x) {
        sWsf[i] = Wsf[i]; sWnf[i] = Wnf[i]; sWsr[i] = Wsr[i]; sWnr[i] = Wnr[i];
    }
    if (threadIdx.x < 64) { sbf[threadIdx.x] = bf[threadIdx.x]; sbr[threadIdx.x] = br[threadIdx.x]; }
    __syncthreads();

    int lane = threadIdx.x & 31;
    int row  = blockIdx.x * 32 + (threadIdx.x >> 5);
    if (row >= NN) return;
    long long base = (long long)row * HID;

    float x0 = d_x[base + lane],       x1 = d_x[base + 32 + lane];
    float f0 = d_nf[base + lane],      f1 = d_nf[base + 32 + lane];
    float r0 = d_nr[base + lane],      r1 = d_nr[base + 32 + lane];
    float af0 = sbf[2 * lane], af1 = sbf[2 * lane + 1];
    float ar0 = sbr[2 * lane], ar1 = sbr[2 * lane + 1];

#pragma unroll 8
    for (int k = 0; k < 32; ++k) {
        float xk = __shfl_sync(0xFFFFFFFFu, x0, k);
        float fk = __shfl_sync(0xFFFFFFFFu, f0, k);
        float rk = __shfl_sync(0xFFFFFFFFu, r0, k);
        float2 wsf = *(const float2*)(sWsf + k * 64 + 2 * lane);
        float2 wnf = *(const float2*)(sWnf + k * 64 + 2 * lane);
        float2 wsr = *(const float2*)(sWsr + k * 64 + 2 * lane);
        float2 wnr = *(const float2*)(sWnr + k * 64 + 2 * lane);
        af0 = fmaf(xk, wsf.x, af0); af1 = fmaf(xk, wsf.y, af1);
        af0 = fmaf(fk, wnf.x, af0); af1 = fmaf(fk, wnf.y, af1);
        ar0 = fmaf(xk, wsr.x, ar0); ar1 = fmaf(xk, wsr.y, ar1);
        ar0 = fmaf(rk, wnr.x, ar0); ar1 = fmaf(rk, wnr.y, ar1);
    }
#pragma unroll 8
    for (int k = 0; k < 32; ++k) {
        float xk = __shfl_sync(0xFFFFFFFFu, x1, k);
        float fk = __shfl_sync(0xFFFFFFFFu, f1, k);
        float rk = __shfl_sync(0xFFFFFFFFu, r1, k);
        int kk = k + 32;
        float2 wsf = *(const float2*)(sWsf + kk * 64 + 2 * lane);
        float2 wnf = *(const float2*)(sWnf + kk * 64 + 2 * lane);
        float2 wsr = *(const float2*)(sWsr + kk * 64 + 2 * lane);
        float2 wnr = *(const float2*)(sWnr + kk * 64 + 2 * lane);
        af0 = fmaf(xk, wsf.x, af0); af1 = fmaf(xk, wsf.y, af1);
        af0 = fmaf(fk, wnf.x, af0); af1 = fmaf(fk, wnf.y, af1);
        ar0 = fmaf(xk, wsr.x, ar0); ar1 = fmaf(xk, wsr.y, ar1);
        ar0 = fmaf(rk, wnr.x, ar0); ar1 = fmaf(rk, wnr.y, ar1);
    }
    float2 xv = *(const float2*)(d_x + base + 2 * lane);
    float u0 = xv.x + fmaxf(af0, 0.f) + fmaxf(ar0, 0.f);
    float u1 = xv.y + fmaxf(af1, 0.f) + fmaxf(ar1, 0.f);
    ((float2*)(d_x + base))[lane] = make_float2(u0, u1);
}

// ---------------- layer 2 fused, batch nodes only + L2-normalize -----------
__global__ void k_batch(const int* __restrict__ ids,
                        const float* __restrict__ Wsf, const float* __restrict__ Wnf,
                        const float* __restrict__ bf,
                        const float* __restrict__ Wsr, const float* __restrict__ Wnr,
                        const float* __restrict__ br,
                        float* __restrict__ out) {
    extern __shared__ float sm[];
    float *sWsf = sm, *sWnf = sm + 4096, *sWsr = sm + 8192, *sWnr = sm + 12288;
    float *sbf  = sm + 16384, *sbr = sm + 16448;
    for (int i = threadIdx.x; i < 4096; i += blockDim.x) {
        sWsf[i] = Wsf[i]; sWnf[i] = Wnf[i]; sWsr[i] = Wsr[i]; sWnr[i] = Wnr[i];
    }
    if (threadIdx.x < 64) { sbf[threadIdx.x] = bf[threadIdx.x]; sbr[threadIdx.x] = br[threadIdx.x]; }
    __syncthreads();

    int lane = threadIdx.x & 31;
    int i = blockIdx.x * (blockDim.x >> 5) + (threadIdx.x >> 5);
    if (i >= NBATCH) return;
    int v = ids[i];

    // forward aggregation at v over x1
    float nf0 = 0.f, nf1 = 0.f;
    int beg = d_row_f[v], end = d_row_f[v + 1];
    for (int e = beg; e < end; ++e) {
        int u = d_enb_f[e]; float wv = d_ew_f[e];
        float2 xv = *(const float2*)(d_x + (long long)u * HID + 2 * lane);
        nf0 = fmaf(wv, xv.x, nf0); nf1 = fmaf(wv, xv.y, nf1);
    }
    float inv = (end > beg) ? 1.0f / (float)(end - beg) : 0.f;
    nf0 *= inv; nf1 *= inv;

    // reverse aggregation
    float nr0 = 0.f, nr1 = 0.f;
    beg = d_row_r[v]; end = d_row_r[v + 1];
    for (int e = beg; e < end; ++e) {
        int u = d_enb_r[e]; float wv = d_ew_r[e];
        float2 xv = *(const float2*)(d_x + (long long)u * HID + 2 * lane);
        nr0 = fmaf(wv, xv.x, nr0); nr1 = fmaf(wv, xv.y, nr1);
    }
    inv = (end > beg) ? 1.0f / (float)(end - beg) : 0.f;
    nr0 *= inv; nr1 *= inv;

    float2 xv = *(const float2*)(d_x + (long long)v * HID + 2 * lane);
    float af0 = sbf[2 * lane], af1 = sbf[2 * lane + 1];
    float ar0 = sbr[2 * lane], ar1 = sbr[2 * lane + 1];

#pragma unroll 4
    for (int k2 = 0; k2 < 32; ++k2) {
        float xa = __shfl_sync(0xFFFFFFFFu, xv.x, k2);
        float xb = __shfl_sync(0xFFFFFFFFu, xv.y, k2);
        float fa = __shfl_sync(0xFFFFFFFFu, nf0, k2);
        float fb = __shfl_sync(0xFFFFFFFFu, nf1, k2);
        float ra = __shfl_sync(0xFFFFFFFFu, nr0, k2);
        float rb = __shfl_sync(0xFFFFFFFFu, nr1, k2);
        int ka = 2 * k2, kb = 2 * k2 + 1;
        float2 w;
        w = *(const float2*)(sWsf + ka * 64 + 2 * lane); af0 = fmaf(xa, w.x, af0); af1 = fmaf(xa, w.y, af1);
        w = *(const float2*)(sWsf + kb * 64 + 2 * lane); af0 = fmaf(xb, w.x, af0); af1 = fmaf(xb, w.y, af1);
        w = *(const float2*)(sWnf + ka * 64 + 2 * lane); af0 = fmaf(fa, w.x, af0); af1 = fmaf(fa, w.y, af1);
        w = *(const float2*)(sWnf + kb * 64 + 2 * lane); af0 = fmaf(fb, w.x, af0); af1 = fmaf(fb, w.y, af1);
        w = *(const float2*)(sWsr + ka * 64 + 2 * lane); ar0 = fmaf(xa, w.x, ar0); ar1 = fmaf(xa, w.y, ar1);
        w = *(const float2*)(sWsr + kb * 64 + 2 * lane); ar0 = fmaf(xb, w.x, ar0); ar1 = fmaf(xb, w.y, ar1);
        w = *(const float2*)(sWnr + ka * 64 + 2 * lane); ar0 = fmaf(ra, w.x, ar0); ar1 = fmaf(ra, w.y, ar1);
        w = *(const float2*)(sWnr + kb * 64 + 2 * lane); ar0 = fmaf(rb, w.x, ar0); ar1 = fmaf(rb, w.y, ar1);
    }
    float u0 = xv.x + fmaxf(af0, 0.f) + fmaxf(ar0, 0.f);
    float u1 = xv.y + fmaxf(af1, 0.f) + fmaxf(ar1, 0.f);
    float ss = u0 * u0 + u1 * u1;
#pragma unroll
    for (int o = 16; o > 0; o >>= 1) ss += __shfl_xor_sync(0xFFFFFFFFu, ss, o);
    float rinv = 1.0f / sqrtf(ss);
    ((float2*)(out + (long long)i * HID))[lane] = make_float2(u0 * rinv, u1 * rinv);
}

// ---------------- launch ----------------------------------------------------
extern "C" void kernel_launch(void* const* d_in, const int* in_sizes, int n_in,
                              void* d_out, int out_size) {
    const float* text = (const float*)d_in[0];
    const float* w    = (const float*)d_in[1];
    const float* Wenc = (const float*)d_in[2];
    const float* benc = (const float*)d_in[3];
    const float* Wsf  = (const float*)d_in[4];
    const float* Wnf  = (const float*)d_in[5];
    const float* bf   = (const float*)d_in[6];
    const float* Wsr  = (const float*)d_in[7];
    const float* Wnr  = (const float*)d_in[8];
    const float* br   = (const float*)d_in[9];
    const int*   src  = (const int*)d_in[10];
    const int*   dst  = (const int*)d_in[11];
    const int*   ids  = (const int*)d_in[12];
    float* out = (float*)d_out;

    const int ENC_SMEM = (TXT * HID + HID) * (int)sizeof(float);       // 98560
    const int UPD_SMEM = (4 * 4096 + 128) * (int)sizeof(float);        // 66048

    cudaFuncSetAttribute(k_encoder, cudaFuncAttributeMaxDynamicSharedMemorySize, ENC_SMEM);
    cudaFuncSetAttribute(k_update,  cudaFuncAttributeMaxDynamicSharedMemorySize, UPD_SMEM);
    cudaFuncSetAttribute(k_batch,   cudaFuncAttributeMaxDynamicSharedMemorySize, UPD_SMEM);

    // CSR build (both directions)
    k_zero<<<(NN + 255) / 256, 256>>>();
    k_hist<<<1024, 256>>>(src, dst);
    k_scan1<<<NB_SCAN, 1024>>>(0);
    k_scan1<<<NB_SCAN, 1024>>>(1);
    k_scan2<<<1, 128>>>(0);
    k_scan2<<<1, 128>>>(1);
    k_scan3<<<(NN + 255) / 256, 256>>>(0);
    k_scan3<<<(NN + 255) / 256, 256>>>(1);
    k_fill<<<1024, 256>>>(src, dst, w);

    // encoder
    k_encoder<<<(NN + 31) / 32, 1024, ENC_SMEM>>>(text, Wenc, benc);

    // layer 0 (dense over all nodes)
    k_agg<<<(NN + 7) / 8, 256>>>(0);
    k_agg<<<(NN + 7) / 8, 256>>>(1);
    k_update<<<(NN + 31) / 32, 1024, UPD_SMEM>>>(Wsf, Wnf, bf, Wsr, Wnr, br);

    // layer 1: only needed at the 1024 output nodes (fused agg+update+norm)
    k_batch<<<NBATCH / 8, 256, UPD_SMEM>>>(ids,
        Wsf + 4096, Wnf + 4096, bf + 64,
        Wsr + 4096, Wnr + 4096, br + 64, out);
}

// round 2
// speedup vs baseline: 3.3561x; 3.3561x over previous
#include <cuda_runtime.h>

#define NN   100000
#define NE   1600000
#define HID  64
#define TXT  384
#define NBATCH 1024
#define NB_SCAN 98            // ceil(NN/1024)

// ---------------- scratch (device globals; no allocation allowed) ----------
__device__ int   d_row_f[NN + 1];
__device__ int   d_row_r[NN + 1];
__device__ int   d_cur_f[NN];
__device__ int   d_cur_r[NN];
__device__ int2  d_e_f[NE];           // (neighbor, weight-bits) fused
__device__ int2  d_e_r[NE];
__device__ float d_x [NN * HID];
__device__ float d_nf[NN * HID];
__device__ float d_nr[NN * HID];
__device__ int   d_bsum[256];

// ---------------- f32x2 helpers ---------------------------------------------
__device__ __forceinline__ unsigned long long pack2(float lo, float hi) {
    unsigned long long r;
    asm("mov.b64 %0, {%1, %2};" : "=l"(r) : "f"(lo), "f"(hi));
    return r;
}
__device__ __forceinline__ void unpack2(unsigned long long v, float& lo, float& hi) {
    asm("mov.b64 {%0, %1}, %2;" : "=f"(lo), "=f"(hi) : "l"(v));
}
__device__ __forceinline__ void fma2(unsigned long long& d,
                                     unsigned long long a, unsigned long long b) {
    asm("fma.rn.f32x2 %0, %1, %2, %0;" : "+l"(d) : "l"(a), "l"(b));
}

// ---------------- CSR construction -----------------------------------------
__global__ void k_zero() {
    int i = blockIdx.x * blockDim.x + threadIdx.x;
    if (i < NN) { d_cur_f[i] = 0; d_cur_r[i] = 0; }
}

__global__ void k_hist(const int* __restrict__ src, const int* __restrict__ dst) {
    for (int e = blockIdx.x * blockDim.x + threadIdx.x; e < NE;
         e += gridDim.x * blockDim.x) {
        atomicAdd(&d_cur_f[dst[e]], 1);
        atomicAdd(&d_cur_r[src[e]], 1);
    }
}

__global__ void k_scan1(int which) {
    const int* cnt = which ? d_cur_r : d_cur_f;
    int*       row = which ? d_row_r : d_row_f;
    __shared__ int s[1024];
    int t = threadIdx.x;
    int i = blockIdx.x * 1024 + t;
    int v = (i < NN) ? cnt[i] : 0;
    s[t] = v; __syncthreads();
    for (int off = 1; off < 1024; off <<= 1) {
        int add = (t >= off) ? s[t - off] : 0;
        __syncthreads();
        s[t] += add;
        __syncthreads();
    }
    if (i < NN) row[i] = s[t] - v;
    if (t == 1023) d_bsum[which * 128 + blockIdx.x] = s[1023];
}

__global__ void k_scan2(int which) {
    __shared__ int s[128];
    int t = threadIdx.x;
    int v = (t < NB_SCAN) ? d_bsum[which * 128 + t] : 0;
    s[t] = v; __syncthreads();
    for (int off = 1; off < 128; off <<= 1) {
        int add = (t >= off) ? s[t - off] : 0;
        __syncthreads();
        s[t] += add;
        __syncthreads();
    }
    d_bsum[which * 128 + t] = s[t] - v;
}

__global__ void k_scan3(int which) {
    int* row = which ? d_row_r : d_row_f;
    int* cur = which ? d_cur_r : d_cur_f;
    int i = blockIdx.x * blockDim.x + threadIdx.x;
    if (i < NN) {
        int r = row[i] + d_bsum[which * 128 + (i >> 10)];
        row[i] = r;
        cur[i] = r;
    }
    if (i == 0) row[NN] = NE;
}

__global__ void k_fill(const int* __restrict__ src, const int* __restrict__ dst,
                       const float* __restrict__ w) {
    for (int e = blockIdx.x * blockDim.x + threadIdx.x; e < NE;
         e += gridDim.x * blockDim.x) {
        int s = src[e], d = dst[e];
        int wb = __float_as_int(w[e]);
        int p = atomicAdd(&d_cur_f[d], 1);
        d_e_f[p] = make_int2(s, wb);
        int q = atomicAdd(&d_cur_r[s], 1);
        d_e_r[q] = make_int2(d, wb);
    }
}

// ---------------- encoder: x = text @ W_enc + b_enc ------------------------
// 128x64 block tile, 128 threads, 8x8 thread tile, f32x2 packed along M.
__global__ __launch_bounds__(128, 4)
void k_enc2(const float* __restrict__ A, const float* __restrict__ W,
            const float* __restrict__ b) {
    __shared__ float sA[32][132];     // [k][row], padded
    __shared__ float sW[32][64];      // [k][col]

    int tid = threadIdx.x;
    int row0 = blockIdx.x * 128;
    int cb = tid & 7;                 // 8 col-blocks
    int rb = tid >> 3;                // 16 row-blocks
    int c0 = cb * 8, r0 = rb * 8;

    unsigned long long acc[4][8];
#pragma unroll
    for (int c = 0; c < 8; ++c) {
        float bv = __ldg(b + c0 + c);
        unsigned long long bp = pack2(bv, bv);
#pragma unroll
        for (int rp = 0; rp < 4; ++rp) acc[rp][c] = bp;
    }

    for (int kc = 0; kc < TXT; kc += 32) {
        // stage A tile transposed: sA[k][row]
#pragma unroll
        for (int p = 0; p < 8; ++p) {
            int lin = tid + p * 128;
            int r = lin >> 3, c4 = (lin & 7) * 4;
            int gr = row0 + r; if (gr >= NN) gr = NN - 1;
            float4 v = *(const float4*)(A + (long long)gr * TXT + kc + c4);
            sA[c4 + 0][r] = v.x; sA[c4 + 1][r] = v.y;
            sA[c4 + 2][r] = v.z; sA[c4 + 3][r] = v.w;
        }
        // stage W chunk
#pragma unroll
        for (int p = 0; p < 4; ++p) {
            int lin = tid + p * 128;
            int k = lin >> 4, cc = (lin & 15) * 4;
            *(float4*)&sW[k][cc] = *(const float4*)(W + (kc + k) * 64 + cc);
        }
        __syncthreads();

#pragma unroll
        for (int k = 0; k < 32; ++k) {
            ulonglong2 aA = *(const ulonglong2*)&sA[k][r0];
            ulonglong2 aB = *(const ulonglong2*)&sA[k][r0 + 4];
            unsigned long long a2[4] = { aA.x, aA.y, aB.x, aB.y };
            float4 w0 = *(const float4*)&sW[k][c0];
            float4 w1 = *(const float4*)&sW[k][c0 + 4];
            float wv[8] = { w0.x, w0.y, w0.z, w0.w, w1.x, w1.y, w1.z, w1.w };
#pragma unroll
            for (int c = 0; c < 8; ++c) {
                unsigned long long w2 = pack2(wv[c], wv[c]);
#pragma unroll
                for (int rp = 0; rp < 4; ++rp) fma2(acc[rp][c], a2[rp], w2);
            }
        }
        __syncthreads();
    }

    // writeback
#pragma unroll
    for (int rp = 0; rp < 4; ++rp) {
#pragma unroll
        for (int h = 0; h < 2; ++h) {
            int gr = row0 + r0 + 2 * rp + h;
            if (gr >= NN) continue;
            float v[8];
#pragma unroll
            for (int c = 0; c < 8; ++c) {
                float lo, hi; unpack2(acc[rp][c], lo, hi);
                v[c] = h ? hi : lo;
            }
            float* op = d_x + (long long)gr * HID + c0;
            *(float4*)op       = make_float4(v[0], v[1], v[2], v[3]);
            *(float4*)(op + 4) = make_float4(v[4], v[5], v[6], v[7]);
        }
    }
}

// ---------------- gather-based mean aggregation ----------------------------
__global__ void k_agg(int which) {
    int lane = threadIdx.x & 31;
    int v = blockIdx.x * (blockDim.x >> 5) + (threadIdx.x >> 5);
    if (v >= NN) return;
    const int*  row = which ? d_row_r : d_row_f;
    const int2* enb = which ? d_e_r   : d_e_f;
    float*      out = which ? d_nr    : d_nf;

    int beg = row[v], end = row[v + 1];
    float a0 = 0.f, a1 = 0.f;
#pragma unroll 4
    for (int e = beg; e < end; ++e) {
        int2 ed = enb[e];
        float wv = __int_as_float(ed.y);
        float2 xv = *(const float2*)(d_x + (long long)ed.x * HID + 2 * lane);
        a0 = fmaf(wv, xv.x, a0);
        a1 = fmaf(wv, xv.y, a1);
    }
    float inv = (end > beg) ? 1.0f / (float)(end - beg) : 0.f;
    ((float2*)(out + (long long)v * HID))[lane] = make_float2(a0 * inv, a1 * inv);
}

// ---------------- dense layer update (layer 0, all nodes, in-place) --------
// x <- x + relu(x@Wsf + nf@Wnf + bf) + relu(x@Wsr + nr@Wnr + br)
// 128x64 block tile, 256 threads, 8x4 thread tile, f32x2 packed along M.
__global__ __launch_bounds__(256, 2)
void k_upd2(const float* __restrict__ Wsf, const float* __restrict__ Wnf,
            const float* __restrict__ bf,
            const float* __restrict__ Wsr, const float* __restrict__ Wnr,
            const float* __restrict__ br) {
    extern __shared__ float sm[];
    float (*sW)[64][64] = (float (*)[64][64])sm;        // 4 x 64 x 64 = 64KB
    float (*sX)[132] = (float (*)[132])(sm + 4 * 4096);
    float (*sF)[132] = (float (*)[132])(sm + 4 * 4096 + 16 * 132);
    float (*sR)[132] = (float (*)[132])(sm + 4 * 4096 + 32 * 132);

    int tid = threadIdx.x;
    int row0 = blockIdx.x * 128;
    int cb = tid & 15;                // 16 col-blocks x 4
    int rb = tid >> 4;                // 16 row-blocks x 8
    int c0 = cb * 4, r0 = rb * 8;

    // stage all weights once
#pragma unroll
    for (int p = 0; p < 16; ++p) {
        int lin = (tid + p * 256) * 4;         // float4 index over 16384 floats
        int m = lin >> 12, rem = lin & 4095;
        const float* srcw = (m == 0) ? Wsf : (m == 1) ? Wnf : (m == 2) ? Wsr : Wnr;
        *(float4*)&sW[m][rem >> 6][rem & 63] = *(const float4*)(srcw + rem);
    }

    unsigned long long accf[4][4], accr[4][4];
#pragma unroll
    for (int c = 0; c < 4; ++c) {
        float bvf = __ldg(bf + c0 + c), bvr = __ldg(br + c0 + c);
        unsigned long long pf = pack2(bvf, bvf), pr = pack2(bvr, bvr);
#pragma unroll
        for (int rp = 0; rp < 4; ++rp) { accf[rp][c] = pf; accr[rp][c] = pr; }
    }

    for (int kc = 0; kc < HID; kc += 16) {
        __syncthreads();
        // stage x/nf/nr tiles transposed: s[k][row], 128 rows x 16 k
#pragma unroll
        for (int p = 0; p < 2; ++p) {
            int lin = tid + p * 256;
            int r = lin >> 2, c4 = (lin & 3) * 4;
            int gr = row0 + r; if (gr >= NN) gr = NN - 1;
            long long base = (long long)gr * HID + kc + c4;
            float4 vx = *(const float4*)(d_x + base);
            float4 vf = *(const float4*)(d_nf + base);
            float4 vr = *(const float4*)(d_nr + base);
            sX[c4 + 0][r] = vx.x; sX[c4 + 1][r] = vx.y; sX[c4 + 2][r] = vx.z; sX[c4 + 3][r] = vx.w;
            sF[c4 + 0][r] = vf.x; sF[c4 + 1][r] = vf.y; sF[c4 + 2][r] = vf.z; sF[c4 + 3][r] = vf.w;
            sR[c4 + 0][r] = vr.x; sR[c4 + 1][r] = vr.y; sR[c4 + 2][r] = vr.z; sR[c4 + 3][r] = vr.w;
        }
        __syncthreads();

#pragma unroll
        for (int k = 0; k < 16; ++k) {
            int gk = kc + k;
            ulonglong2 xA = *(const ulonglong2*)&sX[k][r0];
            ulonglong2 xB = *(const ulonglong2*)&sX[k][r0 + 4];
            ulonglong2 fA = *(const ulonglong2*)&sF[k][r0];
            ulonglong2 fB = *(const ulonglong2*)&sF[k][r0 + 4];
            ulonglong2 rA = *(const ulonglong2*)&sR[k][r0];
            ulonglong2 rB = *(const ulonglong2*)&sR[k][r0 + 4];
            unsigned long long x2[4] = { xA.x, xA.y, xB.x, xB.y };
            unsigned long long f2[4] = { fA.x, fA.y, fB.x, fB.y };
            unsigned long long r2[4] = { rA.x, rA.y, rB.x, rB.y };
            float4 wsf = *(const float4*)&sW[0][gk][c0];
            float4 wnf = *(const float4*)&sW[1][gk][c0];
            float4 wsr = *(const float4*)&sW[2][gk][c0];
            float4 wnr = *(const float4*)&sW[3][gk][c0];
            float vsf[4] = { wsf.x, wsf.y, wsf.z, wsf.w };
            float vnf[4] = { wnf.x, wnf.y, wnf.z, wnf.w };
            float vsr[4] = { wsr.x, wsr.y, wsr.z, wsr.w };
            float vnr[4] = { wnr.x, wnr.y, wnr.z, wnr.w };
#pragma unroll
            for (int c = 0; c < 4; ++c) {
                unsigned long long wsf2 = pack2(vsf[c], vsf[c]);
                unsigned long long wnf2 = pack2(vnf[c], vnf[c]);
                unsigned long long wsr2 = pack2(vsr[c], vsr[c]);
                unsigned long long wnr2 = pack2(vnr[c], vnr[c]);
#pragma unroll
                for (int rp = 0; rp < 4; ++rp) {
                    fma2(accf[rp][c], x2[rp], wsf2);
                    fma2(accf[rp][c], f2[rp], wnf2);
                    fma2(accr[rp][c], x2[rp], wsr2);
                    fma2(accr[rp][c], r2[rp], wnr2);
                }
            }
        }
    }

    // epilogue: x += relu(accf) + relu(accr)
#pragma unroll
    for (int rp = 0; rp < 4; ++rp) {
#pragma unroll
        for (int h = 0; h < 2; ++h) {
            int gr = row0 + r0 + 2 * rp + h;
            if (gr >= NN) continue;
            float* xp = d_x + (long long)gr * HID + c0;
            float4 xv = *(const float4*)xp;
            float vf[4], vr[4];
#pragma unroll
            for (int c = 0; c < 4; ++c) {
                float lo, hi;
                unpack2(accf[rp][c], lo, hi); vf[c] = h ? hi : lo;
                unpack2(accr[rp][c], lo, hi); vr[c] = h ? hi : lo;
            }
            xv.x += fmaxf(vf[0], 0.f) + fmaxf(vr[0], 0.f);
            xv.y += fmaxf(vf[1], 0.f) + fmaxf(vr[1], 0.f);
            xv.z += fmaxf(vf[2], 0.f) + fmaxf(vr[2], 0.f);
            xv.w += fmaxf(vf[3], 0.f) + fmaxf(vr[3], 0.f);
            *(float4*)xp = xv;
        }
    }
}

// ---------------- layer 2 fused, batch nodes only + L2-normalize -----------
__global__ void k_batch(const int* __restrict__ ids,
                        const float* __restrict__ Wsf, const float* __restrict__ Wnf,
                        const float* __restrict__ bf,
                        const float* __restrict__ Wsr, const float* __restrict__ Wnr,
                        const float* __restrict__ br,
                        float* __restrict__ out) {
    extern __shared__ float sm[];
    float *sWsf = sm, *sWnf = sm + 4096, *sWsr = sm + 8192, *sWnr = sm + 12288;
    float *sbf  = sm + 16384, *sbr = sm + 16448;
    for (int i = threadIdx.x; i < 4096; i += blockDim.x) {
        sWsf[i] = Wsf[i]; sWnf[i] = Wnf[i]; sWsr[i] = Wsr[i]; sWnr[i] = Wnr[i];
    }
    if (threadIdx.x < 64) { sbf[threadIdx.x] = bf[threadIdx.x]; sbr[threadIdx.x] = br[threadIdx.x]; }
    __syncthreads();

    int lane = threadIdx.x & 31;
    int i = blockIdx.x * (blockDim.x >> 5) + (threadIdx.x >> 5);
    if (i >= NBATCH) return;
    int v = ids[i];

    float nf0 = 0.f, nf1 = 0.f;
    int beg = d_row_f[v], end = d_row_f[v + 1];
    for (int e = beg; e < end; ++e) {
        int2 ed = d_e_f[e];
        float wv = __int_as_float(ed.y);
        float2 xv = *(const float2*)(d_x + (long long)ed.x * HID + 2 * lane);
        nf0 = fmaf(wv, xv.x, nf0); nf1 = fmaf(wv, xv.y, nf1);
    }
    float inv = (end > beg) ? 1.0f / (float)(end - beg) : 0.f;
    nf0 *= inv; nf1 *= inv;

    float nr0 = 0.f, nr1 = 0.f;
    beg = d_row_r[v]; end = d_row_r[v + 1];
    for (int e = beg; e < end; ++e) {
        int2 ed = d_e_r[e];
        float wv = __int_as_float(ed.y);
        float2 xv = *(const float2*)(d_x + (long long)ed.x * HID + 2 * lane);
        nr0 = fmaf(wv, xv.x, nr0); nr1 = fmaf(wv, xv.y, nr1);
    }
    inv = (end > beg) ? 1.0f / (float)(end - beg) : 0.f;
    nr0 *= inv; nr1 *= inv;

    float2 xv = *(const float2*)(d_x + (long long)v * HID + 2 * lane);
    float af0 = sbf[2 * lane], af1 = sbf[2 * lane + 1];
    float ar0 = sbr[2 * lane], ar1 = sbr[2 * lane + 1];

#pragma unroll 4
    for (int k2 = 0; k2 < 32; ++k2) {
        float xa = __shfl_sync(0xFFFFFFFFu, xv.x, k2);
        float xb = __shfl_sync(0xFFFFFFFFu, xv.y, k2);
        float fa = __shfl_sync(0xFFFFFFFFu, nf0, k2);
        float fb = __shfl_sync(0xFFFFFFFFu, nf1, k2);
        float ra = __shfl_sync(0xFFFFFFFFu, nr0, k2);
        float rb = __shfl_sync(0xFFFFFFFFu, nr1, k2);
        int ka = 2 * k2, kb = 2 * k2 + 1;
        float2 w;
        w = *(const float2*)(sWsf + ka * 64 + 2 * lane); af0 = fmaf(xa, w.x, af0); af1 = fmaf(xa, w.y, af1);
        w = *(const float2*)(sWsf + kb * 64 + 2 * lane); af0 = fmaf(xb, w.x, af0); af1 = fmaf(xb, w.y, af1);
        w = *(const float2*)(sWnf + ka * 64 + 2 * lane); af0 = fmaf(fa, w.x, af0); af1 = fmaf(fa, w.y, af1);
        w = *(const float2*)(sWnf + kb * 64 + 2 * lane); af0 = fmaf(fb, w.x, af0); af1 = fmaf(fb, w.y, af1);
        w = *(const float2*)(sWsr + ka * 64 + 2 * lane); ar0 = fmaf(xa, w.x, ar0); ar1 = fmaf(xa, w.y, ar1);
        w = *(const float2*)(sWsr + kb * 64 + 2 * lane); ar0 = fmaf(xb, w.x, ar0); ar1 = fmaf(xb, w.y, ar1);
        w = *(const float2*)(sWnr + ka * 64 + 2 * lane); ar0 = fmaf(ra, w.x, ar0); ar1 = fmaf(ra, w.y, ar1);
        w = *(const float2*)(sWnr + kb * 64 + 2 * lane); ar0 = fmaf(rb, w.x, ar0); ar1 = fmaf(rb, w.y, ar1);
    }
    float u0 = xv.x + fmaxf(af0, 0.f) + fmaxf(ar0, 0.f);
    float u1 = xv.y + fmaxf(af1, 0.f) + fmaxf(ar1, 0.f);
    float ss = u0 * u0 + u1 * u1;
#pragma unroll
    for (int o = 16; o > 0; o >>= 1) ss += __shfl_xor_sync(0xFFFFFFFFu, ss, o);
    float rinv = 1.0f / sqrtf(ss);
    ((float2*)(out + (long long)i * HID))[lane] = make_float2(u0 * rinv, u1 * rinv);
}

// ---------------- launch ----------------------------------------------------
extern "C" void kernel_launch(void* const* d_in, const int* in_sizes, int n_in,
                              void* d_out, int out_size) {
    const float* text = (const float*)d_in[0];
    const float* w    = (const float*)d_in[1];
    const float* Wenc = (const float*)d_in[2];
    const float* benc = (const float*)d_in[3];
    const float* Wsf  = (const float*)d_in[4];
    const float* Wnf  = (const float*)d_in[5];
    const float* bf   = (const float*)d_in[6];
    const float* Wsr  = (const float*)d_in[7];
    const float* Wnr  = (const float*)d_in[8];
    const float* br   = (const float*)d_in[9];
    const int*   src  = (const int*)d_in[10];
    const int*   dst  = (const int*)d_in[11];
    const int*   ids  = (const int*)d_in[12];
    float* out = (float*)d_out;

    const int UPD_SMEM   = (4 * 4096 + 48 * 132) * (int)sizeof(float);  // 90,880
    const int BATCH_SMEM = (4 * 4096 + 128) * (int)sizeof(float);       // 66,048

    cudaFuncSetAttribute(k_upd2,  cudaFuncAttributeMaxDynamicSharedMemorySize, UPD_SMEM);
    cudaFuncSetAttribute(k_batch, cudaFuncAttributeMaxDynamicSharedMemorySize, BATCH_SMEM);

    // CSR build (both directions)
    k_zero<<<(NN + 255) / 256, 256>>>();
    k_hist<<<1024, 256>>>(src, dst);
    k_scan1<<<NB_SCAN, 1024>>>(0);
    k_scan1<<<NB_SCAN, 1024>>>(1);
    k_scan2<<<1, 128>>>(0);
    k_scan2<<<1, 128>>>(1);
    k_scan3<<<(NN + 255) / 256, 256>>>(0);
    k_scan3<<<(NN + 255) / 256, 256>>>(1);
    k_fill<<<1024, 256>>>(src, dst, w);

    // encoder (register-tiled f32x2 SGEMM)
    k_enc2<<<(NN + 127) / 128, 128>>>(text, Wenc, benc);

    // layer 0 (dense over all nodes)
    k_agg<<<(NN + 7) / 8, 256>>>(0);
    k_agg<<<(NN + 7) / 8, 256>>>(1);
    k_upd2<<<(NN + 127) / 128, 256, UPD_SMEM>>>(Wsf, Wnf, bf, Wsr, Wnr, br);

    // layer 1: only needed at the 1024 output nodes (fused agg+update+norm)
    k_batch<<<NBATCH / 8, 256, BATCH_SMEM>>>(ids,
        Wsf + 4096, Wnf + 4096, bf + 64,
        Wsr + 4096, Wnr + 4096, br + 64, out);
}